// round 12
// baseline (speedup 1.0000x reference)
#include <cuda_runtime.h>
#include <cuda_fp16.h>
#include <cstdint>
#include <math.h>

#define DIMC 768
#define HEADS 12
#define HD 64
#define MLPD 3072
#define BATCH 2
#define SEQ 2048
#define TOKENS (BATCH*SEQ)    // 4096
#define BH (BATCH*HEADS)      // 24
#define QKV_LD (3*DIMC)       // 2304

typedef __half h16;

// ======================= helpers =======================
__device__ __forceinline__ uint32_t smem_u32(const void* p) {
    uint32_t a;
    asm("{ .reg .u64 t; cvta.to.shared.u64 t, %1; cvt.u32.u64 %0, t; }"
        : "=r"(a) : "l"(p));
    return a;
}
__device__ __forceinline__ void ldm_x4(uint32_t (&r)[4], uint32_t addr) {
    asm volatile("ldmatrix.sync.aligned.m8n8.x4.shared.b16 {%0,%1,%2,%3}, [%4];"
        : "=r"(r[0]), "=r"(r[1]), "=r"(r[2]), "=r"(r[3]) : "r"(addr));
}
__device__ __forceinline__ void ldm_x4_t(uint32_t (&r)[4], uint32_t addr) {
    asm volatile("ldmatrix.sync.aligned.m8n8.x4.trans.shared.b16 {%0,%1,%2,%3}, [%4];"
        : "=r"(r[0]), "=r"(r[1]), "=r"(r[2]), "=r"(r[3]) : "r"(addr));
}
__device__ __forceinline__ void mma16816(float (&d)[4], const uint32_t (&a)[4],
                                         uint32_t b0, uint32_t b1) {
    asm volatile("mma.sync.aligned.m16n8k16.row.col.f32.f16.f16.f32 "
        "{%0,%1,%2,%3}, {%4,%5,%6,%7}, {%8,%9}, {%0,%1,%2,%3};"
        : "+f"(d[0]), "+f"(d[1]), "+f"(d[2]), "+f"(d[3])
        : "r"(a[0]), "r"(a[1]), "r"(a[2]), "r"(a[3]), "r"(b0), "r"(b1));
}
__device__ __forceinline__ void split32(float v, h16& h, h16& l) {
    h = __float2half(v);
    l = __float2half(v - __half2float(h));
}
__device__ __forceinline__ void cp16(uint32_t dst, const void* src) {
    asm volatile("cp.async.cg.shared.global [%0], [%1], 16;"
                 :: "r"(dst), "l"(src));
}
#define CP_COMMIT() asm volatile("cp.async.commit_group;" ::: "memory")
#define CP_WAIT0()  asm volatile("cp.async.wait_group 0;" ::: "memory")
#define CP_WAIT2()  asm volatile("cp.async.wait_group 2;" ::: "memory")

__device__ __forceinline__ uint32_t pack_split(float a, float b, uint32_t& lo) {
    h16 ah, al, bh, bl;
    split32(a, ah, al);
    split32(b, bh, bl);
    __half2 H; H.x = ah; H.y = bh;
    __half2 L; L.x = al; L.y = bl;
    lo = *(uint32_t*)&L;
    return *(uint32_t*)&H;
}

// ======================= scratch =======================
__device__ h16   g_ln_h [(size_t)TOKENS*DIMC];
__device__ h16   g_ln_l [(size_t)TOKENS*DIMC];
__device__ h16   g_qkv_h[(size_t)TOKENS*QKV_LD];
__device__ h16   g_qkv_l[(size_t)TOKENS*QKV_LD];
__device__ h16   g_at_h [(size_t)TOKENS*DIMC];
__device__ h16   g_at_l [(size_t)TOKENS*DIMC];
__device__ float g_x1   [(size_t)TOKENS*DIMC];
__device__ h16   g_hh   [(size_t)TOKENS*MLPD];
__device__ h16   g_hl   [(size_t)TOKENS*MLPD];
__device__ h16   g_wqkv_h[(size_t)QKV_LD*DIMC], g_wqkv_l[(size_t)QKV_LD*DIMC];
__device__ h16   g_wpro_h[(size_t)DIMC*DIMC],   g_wpro_l[(size_t)DIMC*DIMC];
__device__ h16   g_w1_h  [(size_t)MLPD*DIMC],   g_w1_l  [(size_t)MLPD*DIMC];
__device__ h16   g_w2_h  [(size_t)DIMC*MLPD],   g_w2_l  [(size_t)DIMC*MLPD];

// ============== merged weight transpose+split (4 matrices, one launch) ==============
struct Wt4 {
    const float* W[4];
    h16* Th[4];
    h16* Tl[4];
    int K[4];
    int N[4];
    int off[5];
};

__global__ void wt4_kernel(Wt4 a)
{
    __shared__ float t[32][33];
    int b = blockIdx.x;
    int mi = 0;
#pragma unroll
    for (int i = 1; i < 4; i++) if (b >= a.off[i]) mi = i;
    int local = b - a.off[mi];
    int ntx = a.N[mi] / 32;
    int nb = (local % ntx) * 32, kb = (local / ntx) * 32;
    const float* W = a.W[mi];
    h16* Th = a.Th[mi];
    h16* Tl = a.Tl[mi];
    int K = a.K[mi], N = a.N[mi];

    int tx = threadIdx.x, ty = threadIdx.y;   // 32 x 8
#pragma unroll
    for (int i = 0; i < 32; i += 8)
        t[ty + i][tx] = W[(size_t)(kb + ty + i) * N + nb + tx];
    __syncthreads();
#pragma unroll
    for (int i = 0; i < 32; i += 8) {
        int n = nb + ty + i, k = kb + tx;
        h16 h, l; split32(t[tx][ty + i], h, l);
        Th[(size_t)n * K + k] = h;
        Tl[(size_t)n * K + k] = l;
    }
}

// ============== LayerNorm -> split fp16 ==============
__global__ void ln_kernel(const float* __restrict__ x,
                          const float* __restrict__ w,
                          const float* __restrict__ b,
                          h16* __restrict__ yh, h16* __restrict__ yl)
{
    int row = blockIdx.x;
    int t = threadIdx.x;
    const float* xr = x + (size_t)row * DIMC;

    float v[3];
    float s = 0.f, ss = 0.f;
#pragma unroll
    for (int i = 0; i < 3; i++) {
        v[i] = xr[t + i * 256];
        s += v[i]; ss += v[i] * v[i];
    }
    __shared__ float rs[256], rss[256];
    rs[t] = s; rss[t] = ss;
    __syncthreads();
    for (int o = 128; o > 0; o >>= 1) {
        if (t < o) { rs[t] += rs[t + o]; rss[t] += rss[t + o]; }
        __syncthreads();
    }
    float mu = rs[0] * (1.0f / DIMC);
    float var = rss[0] * (1.0f / DIMC) - mu * mu;
    float rstd = rsqrtf(var + 1e-5f);
#pragma unroll
    for (int i = 0; i < 3; i++) {
        int c = t + i * 256;
        float o = (v[i] - mu) * rstd * w[c] + b[c];
        h16 h, l; split32(o, h, l);
        yh[(size_t)row * DIMC + c] = h;
        yl[(size_t)row * DIMC + c] = l;
    }
}

// ======================= fused flash attention (unchanged from R8) =======================
__global__ void __launch_bounds__(256, 1)
fattn_kernel(const h16* __restrict__ qkvh, const h16* __restrict__ qkvl,
             h16* __restrict__ Oh, h16* __restrict__ Ol)
{
    constexpr int PAD = 72;
    constexpr int MSZ = 128 * PAD;
    constexpr int KV_OFF = 2 * MSZ;
    constexpr int STG = 4 * MSZ;
    constexpr float SM = 0.125f;

    extern __shared__ h16 smem[];
    const uint32_t sb = smem_u32(smem);
    const int tid = threadIdx.x;
    const int wid = tid >> 5, lane = tid & 31;
    const int m_w = wid * 16;

    const int z = blockIdx.y;
    const int bb = z / HEADS, hh = z % HEADS;
    const int q0 = blockIdx.x * 128;
    const size_t tokbase = (size_t)bb * SEQ;
    const size_t hoff = (size_t)hh * HD;

#pragma unroll
    for (int i = 0; i < 4; i++) {
        int idx = tid + i * 256;
        int r = idx >> 3, c = idx & 7;
        size_t row = (tokbase + q0 + r) * QKV_LD + hoff + c * 8;
        uint32_t d = sb + (uint32_t)(r * PAD + c * 8) * 2;
        cp16(d,            qkvh + row);
        cp16(d + MSZ * 2,  qkvl + row);
    }
#pragma unroll
    for (int i = 0; i < 4; i++) {
        int idx = tid + i * 256;
        int r = idx >> 3, c = idx & 7;
        size_t row = (tokbase + r) * QKV_LD + hoff + c * 8;
        uint32_t d = sb + (uint32_t)(KV_OFF + r * PAD + c * 8) * 2;
        cp16(d,               qkvh + row + DIMC);
        cp16(d + MSZ * 2,     qkvl + row + DIMC);
        cp16(d + 2 * MSZ * 2, qkvh + row + 2 * DIMC);
        cp16(d + 3 * MSZ * 2, qkvl + row + 2 * DIMC);
    }
    CP_COMMIT();
    CP_WAIT0();
    __syncthreads();

    uint32_t qfh[4][4], qfl[4][4];
    {
        const int arow = m_w + (lane & 15);
#pragma unroll
        for (int kc = 0; kc < 4; kc++) {
            const int ak = kc * 16 + ((lane >> 4) << 3);
            uint32_t ad = sb + (uint32_t)(arow * PAD + ak) * 2;
            ldm_x4(qfh[kc], ad);
            ldm_x4(qfl[kc], ad + MSZ * 2);
        }
    }

    float O[8][4];
#pragma unroll
    for (int i = 0; i < 8; i++)
#pragma unroll
        for (int q = 0; q < 4; q++) O[i][q] = 0.f;
    float m0 = -1e30f, m1 = -1e30f, l0 = 0.f, l1 = 0.f;

    const int NT = SEQ / 128;
    for (int t = 0; t < NT; ++t) {
        const int cur = t & 1;

        if (t + 1 < NT) {
            const int s0n = (t + 1) * 128;
            uint32_t base = sb + (uint32_t)(KV_OFF + (cur ^ 1) * STG) * 2;
#pragma unroll
            for (int i = 0; i < 4; i++) {
                int idx = tid + i * 256;
                int r = idx >> 3, c = idx & 7;
                size_t row = (tokbase + s0n + r) * QKV_LD + hoff + c * 8;
                uint32_t d = base + (uint32_t)(r * PAD + c * 8) * 2;
                cp16(d,               qkvh + row + DIMC);
                cp16(d + MSZ * 2,     qkvl + row + DIMC);
                cp16(d + 2 * MSZ * 2, qkvh + row + 2 * DIMC);
                cp16(d + 3 * MSZ * 2, qkvl + row + 2 * DIMC);
            }
            CP_COMMIT();
        }

        const uint32_t kb = sb + (uint32_t)(KV_OFF + cur * STG) * 2;
        const uint32_t vb = kb + 2 * MSZ * 2;

        float acc[16][4];
#pragma unroll
        for (int i = 0; i < 16; i++)
#pragma unroll
            for (int q = 0; q < 4; q++) acc[i][q] = 0.f;

#pragma unroll
        for (int np = 0; np < 8; np++) {
            const int brow = np * 16 + (lane & 7) + ((lane >> 4) << 3);
#pragma unroll
            for (int kc = 0; kc < 4; kc++) {
                const int bk = kc * 16 + ((lane >> 3) & 1) * 8;
                uint32_t ad = kb + (uint32_t)(brow * PAD + bk) * 2;
                uint32_t th[4], tl[4];
                ldm_x4(th, ad);
                ldm_x4(tl, ad + MSZ * 2);
                mma16816(acc[2*np],   qfh[kc], th[0], th[1]);
                mma16816(acc[2*np+1], qfh[kc], th[2], th[3]);
                mma16816(acc[2*np],   qfh[kc], tl[0], tl[1]);
                mma16816(acc[2*np+1], qfh[kc], tl[2], tl[3]);
                mma16816(acc[2*np],   qfl[kc], th[0], th[1]);
                mma16816(acc[2*np+1], qfl[kc], th[2], th[3]);
            }
        }

        float tm0 = -1e30f, tm1 = -1e30f;
#pragma unroll
        for (int i = 0; i < 16; i++) {
            tm0 = fmaxf(tm0, fmaxf(acc[i][0], acc[i][1]));
            tm1 = fmaxf(tm1, fmaxf(acc[i][2], acc[i][3]));
        }
        tm0 = fmaxf(tm0, __shfl_xor_sync(0xffffffffu, tm0, 1));
        tm0 = fmaxf(tm0, __shfl_xor_sync(0xffffffffu, tm0, 2));
        tm1 = fmaxf(tm1, __shfl_xor_sync(0xffffffffu, tm1, 1));
        tm1 = fmaxf(tm1, __shfl_xor_sync(0xffffffffu, tm1, 2));

        float mn0 = fmaxf(m0, SM * tm0);
        float mn1 = fmaxf(m1, SM * tm1);
        float a0 = __expf(m0 - mn0);
        float a1 = __expf(m1 - mn1);
        m0 = mn0; m1 = mn1;

        float rs0 = 0.f, rs1 = 0.f;
#pragma unroll
        for (int i = 0; i < 16; i++) {
            float p0 = __expf(fmaf(SM, acc[i][0], -m0));
            float p1 = __expf(fmaf(SM, acc[i][1], -m0));
            float p2 = __expf(fmaf(SM, acc[i][2], -m1));
            float p3 = __expf(fmaf(SM, acc[i][3], -m1));
            acc[i][0] = p0; acc[i][1] = p1; acc[i][2] = p2; acc[i][3] = p3;
            rs0 += p0 + p1; rs1 += p2 + p3;
        }
        rs0 += __shfl_xor_sync(0xffffffffu, rs0, 1);
        rs0 += __shfl_xor_sync(0xffffffffu, rs0, 2);
        rs1 += __shfl_xor_sync(0xffffffffu, rs1, 1);
        rs1 += __shfl_xor_sync(0xffffffffu, rs1, 2);
        l0 = l0 * a0 + rs0;
        l1 = l1 * a1 + rs1;

#pragma unroll
        for (int i = 0; i < 8; i++) {
            O[i][0] *= a0; O[i][1] *= a0;
            O[i][2] *= a1; O[i][3] *= a1;
        }

#pragma unroll
        for (int kc2 = 0; kc2 < 8; kc2++) {
            uint32_t pah[4], pal[4];
            pah[0] = pack_split(acc[2*kc2][0],   acc[2*kc2][1],   pal[0]);
            pah[1] = pack_split(acc[2*kc2][2],   acc[2*kc2][3],   pal[1]);
            pah[2] = pack_split(acc[2*kc2+1][0], acc[2*kc2+1][1], pal[2]);
            pah[3] = pack_split(acc[2*kc2+1][2], acc[2*kc2+1][3], pal[3]);

            const int vrow = kc2 * 16 + (lane & 15);
#pragma unroll
            for (int dp = 0; dp < 4; dp++) {
                const int vcol = dp * 16 + ((lane >> 4) << 3);
                uint32_t ad = vb + (uint32_t)(vrow * PAD + vcol) * 2;
                uint32_t th[4], tl[4];
                ldm_x4_t(th, ad);
                ldm_x4_t(tl, ad + MSZ * 2);
                mma16816(O[2*dp],   pah, th[0], th[1]);
                mma16816(O[2*dp+1], pah, th[2], th[3]);
                mma16816(O[2*dp],   pah, tl[0], tl[1]);
                mma16816(O[2*dp+1], pah, tl[2], tl[3]);
                mma16816(O[2*dp],   pal, th[0], th[1]);
                mma16816(O[2*dp+1], pal, th[2], th[3]);
            }
        }

        if (t + 1 < NT) {
            CP_WAIT0();
            __syncthreads();
        }
    }

    const float inv0 = 1.0f / l0;
    const float inv1 = 1.0f / l1;
    const int row0 = q0 + m_w + (lane >> 2);
    const int colb = hh * HD + 2 * (lane & 3);
#pragma unroll
    for (int dt = 0; dt < 8; dt++) {
        int col = colb + dt * 8;
        size_t i0 = (tokbase + row0) * DIMC + col;
        size_t i1 = (tokbase + row0 + 8) * DIMC + col;
        uint32_t lo;
        uint32_t hi = pack_split(O[dt][0] * inv0, O[dt][1] * inv0, lo);
        *(uint32_t*)&Oh[i0] = hi;
        *(uint32_t*)&Ol[i0] = lo;
        hi = pack_split(O[dt][2] * inv1, O[dt][3] * inv1, lo);
        *(uint32_t*)&Oh[i1] = hi;
        *(uint32_t*)&Ol[i1] = lo;
    }
}

// ======================= split-fp16 mma.sync GEMM (cp.async 4-stage, BN=64) =======================
enum { ACT_NONE = 0, ACT_GELU = 1 };

template<int ACT, bool HAS_BIAS, bool OUT_SPLIT, bool HAS_RES>
__global__ void __launch_bounds__(256, 1)
mma_gemm(const h16* __restrict__ Ah, const h16* __restrict__ Al, int lda,
         const h16* __restrict__ Bh, const h16* __restrict__ Bl, int ldb,
         float* __restrict__ C, h16* __restrict__ Ch, h16* __restrict__ Cl,
         int ldc, int K,
         const float* __restrict__ bias,
         const float* __restrict__ res, int ldres)
{
    constexpr int BM = 128, BN = 64, BK = 32, PAD = 40, STAGES = 4;
    constexpr int AL_OFF = BM * PAD;
    constexpr int BH_OFF = 2 * BM * PAD;
    constexpr int BL_OFF = 2 * BM * PAD + BN * PAD;
    constexpr int STG    = 2 * BM * PAD + 2 * BN * PAD;   // 15360 halves / stage
    // warps: 4 in M x 2 in N; per-warp tile 32x32: MT=2, NT=4, NP=2
    constexpr int MT = 2, NT = 4, NP = 2;

    extern __shared__ h16 smem[];
    const uint32_t sb = smem_u32(smem);
    const int tid = threadIdx.x;
    const int wid = tid >> 5, lane = tid & 31;
    const int wm = wid >> 1, wn = wid & 1;
    const int m_w = wm * 32, n_w = wn * 32;

    const int m0 = blockIdx.y * BM;
    const int n0 = blockIdx.x * BN;

    float acc[MT][NT][4];
#pragma unroll
    for (int i = 0; i < MT; i++)
#pragma unroll
        for (int j = 0; j < NT; j++)
#pragma unroll
            for (int q = 0; q < 4; q++) acc[i][j][q] = 0.f;

    // ---- async stage loader: chunk c -> slot c % STAGES ----
    // A: 128 rows x 32 halves = 512 x 16B per matrix -> 2 iters x 256 thr
    // B:  64 rows x 32 halves = 256 x 16B per matrix -> 1 iter
    auto load = [&](int c) {
        uint32_t base = sb + (uint32_t)((c % STAGES) * STG) * 2;
        const int k0 = c * BK;
#pragma unroll
        for (int it = 0; it < 2; it++) {
            int idx = tid + it * 256;
            int r = idx >> 2, cc = idx & 3;
            size_t src = (size_t)(m0 + r) * lda + k0 + cc * 8;
            uint32_t d = base + (uint32_t)(r * PAD + cc * 8) * 2;
            cp16(d,              Ah + src);
            cp16(d + AL_OFF * 2, Al + src);
        }
        {
            int r = tid >> 2, cc = tid & 3;
            size_t src = (size_t)(n0 + r) * ldb + k0 + cc * 8;
            uint32_t d = base + (uint32_t)(BH_OFF + r * PAD + cc * 8) * 2;
            cp16(d,                         Bh + src);
            cp16(d + (BL_OFF - BH_OFF) * 2, Bl + src);
        }
        CP_COMMIT();
    };

    const int NC = K / BK;
    load(0); load(1); load(2);

    for (int c = 0; c < NC; ++c) {
        CP_WAIT2();          // with exact 1-commit-per-iter bookkeeping, stage c done
        __syncthreads();

        const uint32_t base = sb + (uint32_t)((c % STAGES) * STG) * 2;
#pragma unroll
        for (int ks = 0; ks < 2; ks++) {
            uint32_t afh[MT][4], afl[MT][4];
            uint32_t bh[NT][2], bl[NT][2];
            const int akoff = ks * 16 + ((lane >> 4) << 3);
#pragma unroll
            for (int mi = 0; mi < MT; mi++) {
                int arow = m_w + mi * 16 + (lane & 15);
                uint32_t ad = base + (uint32_t)(arow * PAD + akoff) * 2;
                ldm_x4(afh[mi], ad);
                ldm_x4(afl[mi], ad + AL_OFF * 2);
            }
            const int brow = n_w + (lane & 7) + ((lane >> 4) << 3);
            const int bkoff = ks * 16 + ((lane >> 3) & 1) * 8;
#pragma unroll
            for (int np = 0; np < NP; np++) {
                uint32_t bd = base + (uint32_t)(BH_OFF + (brow + np * 16) * PAD + bkoff) * 2;
                uint32_t t4[4];
                ldm_x4(t4, bd);
                bh[np*2][0] = t4[0]; bh[np*2][1] = t4[1];
                bh[np*2+1][0] = t4[2]; bh[np*2+1][1] = t4[3];
                ldm_x4(t4, bd + (BL_OFF - BH_OFF) * 2);
                bl[np*2][0] = t4[0]; bl[np*2][1] = t4[1];
                bl[np*2+1][0] = t4[2]; bl[np*2+1][1] = t4[3];
            }
#pragma unroll
            for (int mi = 0; mi < MT; mi++)
#pragma unroll
                for (int ni = 0; ni < NT; ni++)
                    mma16816(acc[mi][ni], afh[mi], bh[ni][0], bh[ni][1]);
#pragma unroll
            for (int mi = 0; mi < MT; mi++)
#pragma unroll
                for (int ni = 0; ni < NT; ni++)
                    mma16816(acc[mi][ni], afh[mi], bl[ni][0], bl[ni][1]);
#pragma unroll
            for (int mi = 0; mi < MT; mi++)
#pragma unroll
                for (int ni = 0; ni < NT; ni++)
                    mma16816(acc[mi][ni], afl[mi], bh[ni][0], bh[ni][1]);
        }

        // exactly one commit per iteration keeps wait_group 2 == "stage c done"
        if (c + 3 < NC) load(c + 3);
        else            CP_COMMIT();   // empty group for tail drain accounting
    }

    // ---- epilogue ----
#pragma unroll
    for (int mi = 0; mi < MT; mi++) {
#pragma unroll
        for (int ni = 0; ni < NT; ni++) {
            int row0 = m0 + m_w + mi * 16 + (lane >> 2);
            int col  = n0 + n_w + ni * 8 + 2 * (lane & 3);
#pragma unroll
            for (int half = 0; half < 2; half++) {
                int row = row0 + half * 8;
                float v0 = acc[mi][ni][half * 2 + 0];
                float v1 = acc[mi][ni][half * 2 + 1];
                if (HAS_BIAS) {
                    float2 bb = *(const float2*)&bias[col];
                    v0 += bb.x; v1 += bb.y;
                }
                if (ACT == ACT_GELU) {
                    v0 = 0.5f * v0 * (1.0f + erff(v0 * 0.70710678118654752f));
                    v1 = 0.5f * v1 * (1.0f + erff(v1 * 0.70710678118654752f));
                }
                if (HAS_RES) {
                    float2 rr = *(const float2*)&res[(size_t)row * ldres + col];
                    v0 += rr.x; v1 += rr.y;
                }
                size_t idx = (size_t)row * ldc + col;
                if (!OUT_SPLIT) {
                    *(float2*)&C[idx] = make_float2(v0, v1);
                } else {
                    uint32_t lo;
                    uint32_t hi = pack_split(v0, v1, lo);
                    *(uint32_t*)&Ch[idx] = hi;
                    *(uint32_t*)&Cl[idx] = lo;
                }
            }
        }
    }
}

// ======================= host launcher =======================
extern "C" void kernel_launch(void* const* d_in, const int* in_sizes, int n_in,
                              void* d_out, int out_size)
{
    const float* x      = (const float*)d_in[0];
    const float* ln1_w  = (const float*)d_in[1];
    const float* ln1_b  = (const float*)d_in[2];
    const float* qkv_w  = (const float*)d_in[3];
    const float* qkv_b  = (const float*)d_in[4];
    const float* proj_w = (const float*)d_in[5];
    const float* proj_b = (const float*)d_in[6];
    const float* ln2_w  = (const float*)d_in[7];
    const float* ln2_b  = (const float*)d_in[8];
    const float* lin1_w = (const float*)d_in[9];
    const float* lin1_b = (const float*)d_in[10];
    const float* lin2_w = (const float*)d_in[11];
    const float* lin2_b = (const float*)d_in[12];
    float* out = (float*)d_out;

    h16 *ln_h, *ln_l, *qkv_h, *qkv_l, *at_h, *at_l, *h_h, *h_l;
    h16 *wqkv_h, *wqkv_l, *wpro_h, *wpro_l, *w1_h, *w1_l, *w2_h, *w2_l;
    float *x1;
    cudaGetSymbolAddress((void**)&ln_h, g_ln_h);   cudaGetSymbolAddress((void**)&ln_l, g_ln_l);
    cudaGetSymbolAddress((void**)&qkv_h, g_qkv_h); cudaGetSymbolAddress((void**)&qkv_l, g_qkv_l);
    cudaGetSymbolAddress((void**)&at_h, g_at_h);   cudaGetSymbolAddress((void**)&at_l, g_at_l);
    cudaGetSymbolAddress((void**)&x1, g_x1);
    cudaGetSymbolAddress((void**)&h_h, g_hh);      cudaGetSymbolAddress((void**)&h_l, g_hl);
    cudaGetSymbolAddress((void**)&wqkv_h, g_wqkv_h); cudaGetSymbolAddress((void**)&wqkv_l, g_wqkv_l);
    cudaGetSymbolAddress((void**)&wpro_h, g_wpro_h); cudaGetSymbolAddress((void**)&wpro_l, g_wpro_l);
    cudaGetSymbolAddress((void**)&w1_h, g_w1_h);   cudaGetSymbolAddress((void**)&w1_l, g_w1_l);
    cudaGetSymbolAddress((void**)&w2_h, g_w2_h);   cudaGetSymbolAddress((void**)&w2_l, g_w2_l);

    const int SMGEMM = 4 * (2 * 128 * 40 + 2 * 64 * 40) * 2;  // 122880
    const int SMATT  = (2 + 8) * 128 * 72 * 2;                // 184320

    auto* kQKV  = mma_gemm<ACT_NONE, true,  true,  false>;
    auto* kPROJ = mma_gemm<ACT_NONE, true,  false, true >;   // also lin2
    auto* kLIN1 = mma_gemm<ACT_GELU, true,  true,  false>;

    cudaFuncSetAttribute(kQKV,  cudaFuncAttributeMaxDynamicSharedMemorySize, SMGEMM);
    cudaFuncSetAttribute(kPROJ, cudaFuncAttributeMaxDynamicSharedMemorySize, SMGEMM);
    cudaFuncSetAttribute(kLIN1, cudaFuncAttributeMaxDynamicSharedMemorySize, SMGEMM);
    cudaFuncSetAttribute(fattn_kernel, cudaFuncAttributeMaxDynamicSharedMemorySize, SMATT);

    // 0) merged weight transposes+splits (one launch, 4 matrices in parallel)
    Wt4 wa;
    wa.W[0] = qkv_w;  wa.Th[0] = wqkv_h; wa.Tl[0] = wqkv_l; wa.K[0] = DIMC; wa.N[0] = QKV_LD;
    wa.W[1] = proj_w; wa.Th[1] = wpro_h; wa.Tl[1] = wpro_l; wa.K[1] = DIMC; wa.N[1] = DIMC;
    wa.W[2] = lin1_w; wa.Th[2] = w1_h;   wa.Tl[2] = w1_l;   wa.K[2] = DIMC; wa.N[2] = MLPD;
    wa.W[3] = lin2_w; wa.Th[3] = w2_h;   wa.Tl[3] = w2_l;   wa.K[3] = MLPD; wa.N[3] = DIMC;
    int t0 = (QKV_LD/32)*(DIMC/32);   // 1728
    int t1 = (DIMC/32)*(DIMC/32);     // 576
    int t2 = (MLPD/32)*(DIMC/32);     // 2304
    int t3 = (DIMC/32)*(MLPD/32);     // 2304
    wa.off[0] = 0; wa.off[1] = t0; wa.off[2] = t0+t1; wa.off[3] = t0+t1+t2; wa.off[4] = t0+t1+t2+t3;
    wt4_kernel<<<wa.off[4], dim3(32,8)>>>(wa);

    // 1) LN1
    ln_kernel<<<TOKENS, 256>>>(x, ln1_w, ln1_b, ln_h, ln_l);

    // 2) qkv = ln @ qkv_w + qkv_b
    kQKV<<<dim3(QKV_LD/64, TOKENS/128), 256, SMGEMM>>>(
        ln_h, ln_l, DIMC, wqkv_h, wqkv_l, DIMC,
        nullptr, qkv_h, qkv_l, QKV_LD, DIMC, qkv_b, nullptr, 0);

    // 3) fused attention
    fattn_kernel<<<dim3(SEQ/128, BH), 256, SMATT>>>(qkv_h, qkv_l, at_h, at_l);

    // 4) x1 = attn @ proj_w + proj_b + x
    kPROJ<<<dim3(DIMC/64, TOKENS/128), 256, SMGEMM>>>(
        at_h, at_l, DIMC, wpro_h, wpro_l, DIMC,
        x1, nullptr, nullptr, DIMC, DIMC, proj_b, x, DIMC);

    // 5) LN2
    ln_kernel<<<TOKENS, 256>>>(x1, ln2_w, ln2_b, ln_h, ln_l);

    // 6) h = gelu(ln @ lin1_w + lin1_b)
    kLIN1<<<dim3(MLPD/64, TOKENS/128), 256, SMGEMM>>>(
        ln_h, ln_l, DIMC, w1_h, w1_l, DIMC,
        nullptr, h_h, h_l, MLPD, DIMC, lin1_b, nullptr, 0);

    // 7) out = h @ lin2_w + lin2_b + x1
    kPROJ<<<dim3(DIMC/64, TOKENS/128), 256, SMGEMM>>>(
        h_h, h_l, MLPD, w2_h, w2_l, MLPD,
        out, nullptr, nullptr, DIMC, MLPD, lin2_b, x1, DIMC);
}